// round 1
// baseline (speedup 1.0000x reference)
#include <cuda_runtime.h>
#include <cuda_bf16.h>

// Problem constants
#define BATCH 2
#define SEQ   2048
#define DIM   1024
#define HEADS 16
#define HDIM  64
#define MROWS (BATCH * SEQ)   // 4096

// Scratch (allocation-free rule: __device__ globals)
__device__ float g_Q[BATCH * HEADS * SEQ * HDIM];   // [B,H,S,DH]
__device__ float g_K[BATCH * HEADS * SEQ * HDIM];
__device__ float g_V[BATCH * HEADS * SEQ * HDIM];
__device__ float g_ctx[BATCH * SEQ * DIM];          // [B,S,H*DH]

// ---------------------------------------------------------------------------
// SGEMM: C[M=4096, N=1024] = A[4096,1024] @ W[1024,1024] + bias
// 128x128x8 tile, 256 threads, 8x8 per-thread microtile.
// MODE 0: plain row-major write. MODE 1: split-head write to [B,H,S,DH].
// ---------------------------------------------------------------------------
template <int MODE>
__global__ __launch_bounds__(256)
void sgemm_bias(const float* __restrict__ A,
                const float* __restrict__ W,
                const float* __restrict__ bias,
                float* __restrict__ C)
{
    const int K = DIM;
    __shared__ float As[8][128];   // transposed A tile
    __shared__ float Bs[8][128];

    const int tid = threadIdx.x;
    const int bm  = blockIdx.y;    // 0..31
    const int bn  = blockIdx.x;    // 0..7

    const int tx = tid & 15;       // 0..15
    const int ty = tid >> 4;       // 0..15

    // A-load mapping: each thread loads 1 float4
    const int aRow = tid >> 1;             // 0..127
    const int aCol = (tid & 1) * 4;        // 0 or 4
    // B-load mapping
    const int bRow = tid >> 5;             // 0..7
    const int bCol = (tid & 31) * 4;       // 0..124

    const float* Aptr = A + (size_t)(bm * 128 + aRow) * K + aCol;
    const float* Wptr = W + (size_t)bRow * DIM + bn * 128 + bCol;

    float acc[8][8];
#pragma unroll
    for (int i = 0; i < 8; i++)
#pragma unroll
        for (int j = 0; j < 8; j++) acc[i][j] = 0.f;

    for (int k0 = 0; k0 < K; k0 += 8) {
        // load A tile (transposed into As[k][m])
        float4 a = *reinterpret_cast<const float4*>(Aptr + k0);
        As[aCol + 0][aRow] = a.x;
        As[aCol + 1][aRow] = a.y;
        As[aCol + 2][aRow] = a.z;
        As[aCol + 3][aRow] = a.w;
        // load B tile
        float4 b = *reinterpret_cast<const float4*>(Wptr + (size_t)k0 * DIM);
        *reinterpret_cast<float4*>(&Bs[bRow][bCol]) = b;
        __syncthreads();

#pragma unroll
        for (int k = 0; k < 8; k++) {
            float4 ra0 = *reinterpret_cast<const float4*>(&As[k][ty * 8]);
            float4 ra1 = *reinterpret_cast<const float4*>(&As[k][ty * 8 + 4]);
            float4 rb0 = *reinterpret_cast<const float4*>(&Bs[k][tx * 8]);
            float4 rb1 = *reinterpret_cast<const float4*>(&Bs[k][tx * 8 + 4]);
            float ra[8] = {ra0.x, ra0.y, ra0.z, ra0.w, ra1.x, ra1.y, ra1.z, ra1.w};
            float rb[8] = {rb0.x, rb0.y, rb0.z, rb0.w, rb1.x, rb1.y, rb1.z, rb1.w};
#pragma unroll
            for (int i = 0; i < 8; i++)
#pragma unroll
                for (int j = 0; j < 8; j++)
                    acc[i][j] = fmaf(ra[i], rb[j], acc[i][j]);
        }
        __syncthreads();
    }

    // Epilogue
#pragma unroll
    for (int i = 0; i < 8; i++) {
        const int m = bm * 128 + ty * 8 + i;
        if (MODE == 0) {
#pragma unroll
            for (int j4 = 0; j4 < 8; j4 += 4) {
                const int n = bn * 128 + tx * 8 + j4;
                float4 v;
                v.x = acc[i][j4 + 0] + bias[n + 0];
                v.y = acc[i][j4 + 1] + bias[n + 1];
                v.z = acc[i][j4 + 2] + bias[n + 2];
                v.w = acc[i][j4 + 3] + bias[n + 3];
                *reinterpret_cast<float4*>(&C[(size_t)m * DIM + n]) = v;
            }
        } else {
            const int b = m >> 11;        // /SEQ
            const int s = m & (SEQ - 1);
#pragma unroll
            for (int j = 0; j < 8; j++) {
                const int n = bn * 128 + tx * 8 + j;
                const int h = n >> 6;
                const int d = n & 63;
                C[(((size_t)(b * HEADS + h)) * SEQ + s) * HDIM + d] =
                    acc[i][j] + bias[n];
            }
        }
    }
}

// ---------------------------------------------------------------------------
// Flash attention (fp32). Grid: (S/128, H, B). 128 threads; thread = 1 query.
// Q,K,V in [B,H,S,DH]; writes ctx in [B,S,H*DH].
// ---------------------------------------------------------------------------
__global__ __launch_bounds__(128)
void flash_attn(const float* __restrict__ Q,
                const float* __restrict__ Kk,
                const float* __restrict__ V,
                const float* __restrict__ mask,
                float* __restrict__ ctx)
{
    __shared__ float4 Ks[64][16];
    __shared__ float4 Vs[64][16];
    __shared__ float  mk[64];

    const int tid = threadIdx.x;
    const int qt  = blockIdx.x;
    const int h   = blockIdx.y;
    const int b   = blockIdx.z;

    const int q = qt * 128 + tid;                  // query index in sequence
    const size_t headBase = ((size_t)(b * HEADS + h)) * SEQ;  // rows of this head

    // load q row into registers
    float4 qv[16];
    const float4* Q4 = reinterpret_cast<const float4*>(Q + (headBase + q) * HDIM);
#pragma unroll
    for (int c = 0; c < 16; c++) qv[c] = Q4[c];

    float4 acc[16];
#pragma unroll
    for (int c = 0; c < 16; c++) acc[c] = make_float4(0.f, 0.f, 0.f, 0.f);
    float mmax = -1e30f;
    float l = 0.f;

    const float4* K4 = reinterpret_cast<const float4*>(Kk);
    const float4* V4 = reinterpret_cast<const float4*>(V);

    for (int kt = 0; kt < SEQ / 64; kt++) {
        __syncthreads();
        // cooperative load of 64x64 K and V tiles (1024 float4 each)
#pragma unroll
        for (int r = 0; r < 8; r++) {
            const int idx = r * 128 + tid;         // 0..1023
            const int row = idx >> 4;
            const int c   = idx & 15;
            const size_t g = (headBase + kt * 64 + row) * 16 + c;
            Ks[row][c] = K4[g];
            Vs[row][c] = V4[g];
        }
        if (tid < 64) mk[tid] = mask[(size_t)b * SEQ + kt * 64 + tid];
        __syncthreads();

#pragma unroll 4
        for (int j = 0; j < 64; j++) {
            float4 s4 = make_float4(0.f, 0.f, 0.f, 0.f);
#pragma unroll
            for (int c = 0; c < 16; c++) {
                float4 kk = Ks[j][c];
                s4.x = fmaf(qv[c].x, kk.x, s4.x);
                s4.y = fmaf(qv[c].y, kk.y, s4.y);
                s4.z = fmaf(qv[c].z, kk.z, s4.z);
                s4.w = fmaf(qv[c].w, kk.w, s4.w);
            }
            float s = (s4.x + s4.y + s4.z + s4.w) * 0.125f
                      - 1000000.0f * (1.0f - mk[j]);
            if (s > mmax) {
                const float corr = __expf(mmax - s);
                l *= corr;
#pragma unroll
                for (int c = 0; c < 16; c++) {
                    acc[c].x *= corr; acc[c].y *= corr;
                    acc[c].z *= corr; acc[c].w *= corr;
                }
                mmax = s;
            }
            const float p = __expf(s - mmax);
            l += p;
#pragma unroll
            for (int c = 0; c < 16; c++) {
                float4 vv = Vs[j][c];
                acc[c].x = fmaf(p, vv.x, acc[c].x);
                acc[c].y = fmaf(p, vv.y, acc[c].y);
                acc[c].z = fmaf(p, vv.z, acc[c].z);
                acc[c].w = fmaf(p, vv.w, acc[c].w);
            }
        }
    }

    const float inv = 1.0f / l;
    float4* out4 = reinterpret_cast<float4*>(ctx) +
                   ((size_t)(b * SEQ + q) * DIM + h * HDIM) / 4;
#pragma unroll
    for (int c = 0; c < 16; c++) {
        float4 v = acc[c];
        v.x *= inv; v.y *= inv; v.z *= inv; v.w *= inv;
        out4[c] = v;
    }
}

// ---------------------------------------------------------------------------
// Launch
// ---------------------------------------------------------------------------
extern "C" void kernel_launch(void* const* d_in, const int* in_sizes, int n_in,
                              void* d_out, int out_size)
{
    const float* X    = (const float*)d_in[0];
    const float* mask = (const float*)d_in[1];
    const float* Wq   = (const float*)d_in[2];
    const float* bq   = (const float*)d_in[3];
    const float* Wk   = (const float*)d_in[4];
    const float* bk   = (const float*)d_in[5];
    const float* Wv   = (const float*)d_in[6];
    const float* bv   = (const float*)d_in[7];
    const float* Wo   = (const float*)d_in[8];
    const float* bo   = (const float*)d_in[9];
    float* out = (float*)d_out;

    float *Qp, *Kp, *Vp, *Cp;
    cudaGetSymbolAddress((void**)&Qp, g_Q);
    cudaGetSymbolAddress((void**)&Kp, g_K);
    cudaGetSymbolAddress((void**)&Vp, g_V);
    cudaGetSymbolAddress((void**)&Cp, g_ctx);

    dim3 gemmGrid(DIM / 128, MROWS / 128);   // (8, 32)
    sgemm_bias<1><<<gemmGrid, 256>>>(X, Wq, bq, Qp);
    sgemm_bias<1><<<gemmGrid, 256>>>(X, Wk, bk, Kp);
    sgemm_bias<1><<<gemmGrid, 256>>>(X, Wv, bv, Vp);

    dim3 attnGrid(SEQ / 128, HEADS, BATCH);  // (16, 16, 2)
    flash_attn<<<attnGrid, 128>>>(Qp, Kp, Vp, mask, Cp);

    sgemm_bias<0><<<gemmGrid, 256>>>(Cp, Wo, bo, out);
}

// round 3
// speedup vs baseline: 1.7318x; 1.7318x over previous
#include <cuda_runtime.h>
#include <cuda_bf16.h>

// Problem constants
#define BATCH 2
#define SEQ   2048
#define DIM   1024
#define HEADS 16
#define HDIM  64
#define MROWS (BATCH * SEQ)   // 4096

typedef unsigned long long u64;

// Scratch (allocation-free rule: __device__ globals)
__device__ float g_Q[BATCH * HEADS * SEQ * HDIM];   // [B,H,S,DH]
__device__ float g_K[BATCH * HEADS * SEQ * HDIM];
__device__ float g_V[BATCH * HEADS * SEQ * HDIM];
__device__ float g_ctx[BATCH * SEQ * DIM];          // [B,S,H*DH]

// ---------------------------------------------------------------------------
// Helpers
// ---------------------------------------------------------------------------
__device__ __forceinline__ void mma_bf16(float4& d,
                                         unsigned a0, unsigned a1, unsigned a2, unsigned a3,
                                         unsigned b0, unsigned b1)
{
    asm volatile("mma.sync.aligned.m16n8k16.row.col.f32.bf16.bf16.f32 "
                 "{%0,%1,%2,%3}, {%4,%5,%6,%7}, {%8,%9}, {%0,%1,%2,%3};"
                 : "+f"(d.x), "+f"(d.y), "+f"(d.z), "+f"(d.w)
                 : "r"(a0), "r"(a1), "r"(a2), "r"(a3), "r"(b0), "r"(b1));
}

// split fp32 pair into packed bf16x2 (hi) and bf16x2 (lo = residual)
__device__ __forceinline__ void split_pack(float x, float y, unsigned& hi, unsigned& lo)
{
    __nv_bfloat16 bx = __float2bfloat16(x);
    __nv_bfloat16 by = __float2bfloat16(y);
    float lx = x - __bfloat162float(bx);
    float ly = y - __bfloat162float(by);
    __nv_bfloat162 h = __halves2bfloat162(bx, by);
    __nv_bfloat162 l = __floats2bfloat162_rn(lx, ly);
    hi = reinterpret_cast<unsigned&>(h);
    lo = reinterpret_cast<unsigned&>(l);
}

__device__ __forceinline__ void ffma2(u64& d, u64 a, u64 b)
{   // d = a*b + d (packed 2x f32)
    asm volatile("fma.rn.f32x2 %0, %1, %2, %0;" : "+l"(d) : "l"(a), "l"(b));
}
__device__ __forceinline__ void fmul2(u64& d, u64 a, u64 b)
{
    asm volatile("mul.rn.f32x2 %0, %1, %2;" : "=l"(d) : "l"(a), "l"(b));
}
__device__ __forceinline__ u64 pack2(float x, float y)
{
    u64 r;
    asm volatile("mov.b64 %0, {%1, %2};" : "=l"(r) : "f"(x), "f"(y));
    return r;
}
__device__ __forceinline__ void unpack2(u64 v, float& x, float& y)
{
    asm volatile("mov.b64 {%0, %1}, %2;" : "=f"(x), "=f"(y) : "l"(v));
}

// ---------------------------------------------------------------------------
// GEMM via bf16-split tensor-core mma (3-term compensated, ~1e-5 rel err)
// C[4096,1024] = A[4096,1024] @ W[1024,1024] + bias
// Block tile 128x128xBK16, 256 threads, 8 warps in 4(m) x 2(n) grid,
// warp tile 32x64. Double-buffered smem.
// MODE 0: row-major write. MODE 1: split-head write to [B,H,S,DH].
// ---------------------------------------------------------------------------
#define SSTRIDE 136   // smem row stride in bf16x2 units (conflict-free frag loads)

template <int MODE>
__global__ __launch_bounds__(256, 2)
void gemm_bf16s(const float* __restrict__ A,
                const float* __restrict__ W,
                const float* __restrict__ bias,
                float* __restrict__ C)
{
    // [buf][k2 (0..7)][m or n (0..127)] packed bf16x2 along k
    __shared__ unsigned AsH[2][8 * SSTRIDE];
    __shared__ unsigned AsL[2][8 * SSTRIDE];
    __shared__ unsigned BsH[2][8 * SSTRIDE];
    __shared__ unsigned BsL[2][8 * SSTRIDE];

    const int tid   = threadIdx.x;
    const int lane  = tid & 31;
    const int warp  = tid >> 5;
    const int warpM = warp >> 1;     // 0..3
    const int warpN = warp & 1;      // 0..1
    const int g     = lane >> 2;     // 0..7
    const int tig   = lane & 3;      // 0..3

    const int bm = blockIdx.y;
    const int bn = blockIdx.x;

    // A load mapping: 2 float4 per thread
    const int aRow = tid >> 2;        // 0..63 (second load +64)
    const int aK4  = tid & 3;         // float4 index along k (cols aK4*4..+3)
    // B load mapping: 4 pairs per thread, each pair = 2 scalar rows
    const int bN  = tid & 127;        // n within tile
    const int bK2 = tid >> 7;         // 0..1 (then +2,+4,+6)

    float4 ra[2];
    float  rb[4][2];

    // ---- prologue: load tile 0 ----
    {
        const float* Ap = A + (size_t)(bm * 128 + aRow) * DIM + aK4 * 4;
        ra[0] = *reinterpret_cast<const float4*>(Ap);
        ra[1] = *reinterpret_cast<const float4*>(Ap + (size_t)64 * DIM);
#pragma unroll
        for (int p = 0; p < 4; p++) {
            const int k2 = bK2 + 2 * p;
            const float* Wp = W + (size_t)(2 * k2) * DIM + bn * 128 + bN;
            rb[p][0] = Wp[0];
            rb[p][1] = Wp[DIM];
        }
    }
    // store tile 0 into buf 0
    {
#pragma unroll
        for (int p = 0; p < 2; p++) {
            const int m = aRow + 64 * p;
            unsigned h0, l0, h1, l1;
            split_pack(ra[p].x, ra[p].y, h0, l0);
            split_pack(ra[p].z, ra[p].w, h1, l1);
            AsH[0][(aK4 * 2 + 0) * SSTRIDE + m] = h0;
            AsL[0][(aK4 * 2 + 0) * SSTRIDE + m] = l0;
            AsH[0][(aK4 * 2 + 1) * SSTRIDE + m] = h1;
            AsL[0][(aK4 * 2 + 1) * SSTRIDE + m] = l1;
        }
#pragma unroll
        for (int p = 0; p < 4; p++) {
            const int k2 = bK2 + 2 * p;
            unsigned h, l;
            split_pack(rb[p][0], rb[p][1], h, l);
            BsH[0][k2 * SSTRIDE + bN] = h;
            BsL[0][k2 * SSTRIDE + bN] = l;
        }
    }
    __syncthreads();

    float4 acc[2][8];
#pragma unroll
    for (int i = 0; i < 2; i++)
#pragma unroll
        for (int j = 0; j < 8; j++) acc[i][j] = make_float4(0.f, 0.f, 0.f, 0.f);

    const int NK = DIM / 16;   // 64
    for (int kt = 0; kt < NK; kt++) {
        const int buf = kt & 1;

        // issue global loads for next tile (latency overlaps compute)
        if (kt < NK - 1) {
            const int k0 = (kt + 1) * 16;
            const float* Ap = A + (size_t)(bm * 128 + aRow) * DIM + k0 + aK4 * 4;
            ra[0] = *reinterpret_cast<const float4*>(Ap);
            ra[1] = *reinterpret_cast<const float4*>(Ap + (size_t)64 * DIM);
#pragma unroll
            for (int p = 0; p < 4; p++) {
                const int k2 = bK2 + 2 * p;
                const float* Wp = W + (size_t)(k0 + 2 * k2) * DIM + bn * 128 + bN;
                rb[p][0] = Wp[0];
                rb[p][1] = Wp[DIM];
            }
        }

        // ---- compute on buf ----
        unsigned aH[2][4], aL[2][4];
#pragma unroll
        for (int mb = 0; mb < 2; mb++) {
            const int m0 = warpM * 32 + mb * 16 + g;
            aH[mb][0] = AsH[buf][tig * SSTRIDE + m0];
            aH[mb][1] = AsH[buf][tig * SSTRIDE + m0 + 8];
            aH[mb][2] = AsH[buf][(tig + 4) * SSTRIDE + m0];
            aH[mb][3] = AsH[buf][(tig + 4) * SSTRIDE + m0 + 8];
            aL[mb][0] = AsL[buf][tig * SSTRIDE + m0];
            aL[mb][1] = AsL[buf][tig * SSTRIDE + m0 + 8];
            aL[mb][2] = AsL[buf][(tig + 4) * SSTRIDE + m0];
            aL[mb][3] = AsL[buf][(tig + 4) * SSTRIDE + m0 + 8];
        }
#pragma unroll
        for (int nb = 0; nb < 8; nb++) {
            const int n0 = warpN * 64 + nb * 8 + g;
            const unsigned bh0 = BsH[buf][tig * SSTRIDE + n0];
            const unsigned bh1 = BsH[buf][(tig + 4) * SSTRIDE + n0];
            const unsigned bl0 = BsL[buf][tig * SSTRIDE + n0];
            const unsigned bl1 = BsL[buf][(tig + 4) * SSTRIDE + n0];
#pragma unroll
            for (int mb = 0; mb < 2; mb++) {
                mma_bf16(acc[mb][nb], aH[mb][0], aH[mb][1], aH[mb][2], aH[mb][3], bh0, bh1);
                mma_bf16(acc[mb][nb], aH[mb][0], aH[mb][1], aH[mb][2], aH[mb][3], bl0, bl1);
                mma_bf16(acc[mb][nb], aL[mb][0], aL[mb][1], aL[mb][2], aL[mb][3], bh0, bh1);
            }
        }

        // store next tile into other buffer
        if (kt < NK - 1) {
            const int nbuf = buf ^ 1;
#pragma unroll
            for (int p = 0; p < 2; p++) {
                const int m = aRow + 64 * p;
                unsigned h0, l0, h1, l1;
                split_pack(ra[p].x, ra[p].y, h0, l0);
                split_pack(ra[p].z, ra[p].w, h1, l1);
                AsH[nbuf][(aK4 * 2 + 0) * SSTRIDE + m] = h0;
                AsL[nbuf][(aK4 * 2 + 0) * SSTRIDE + m] = l0;
                AsH[nbuf][(aK4 * 2 + 1) * SSTRIDE + m] = h1;
                AsL[nbuf][(aK4 * 2 + 1) * SSTRIDE + m] = l1;
            }
#pragma unroll
            for (int p = 0; p < 4; p++) {
                const int k2 = bK2 + 2 * p;
                unsigned h, l;
                split_pack(rb[p][0], rb[p][1], h, l);
                BsH[nbuf][k2 * SSTRIDE + bN] = h;
                BsL[nbuf][k2 * SSTRIDE + bN] = l;
            }
        }
        __syncthreads();
    }

    // ---- epilogue ----
#pragma unroll
    for (int mb = 0; mb < 2; mb++) {
        const int row0 = bm * 128 + warpM * 32 + mb * 16 + g;
#pragma unroll
        for (int nb = 0; nb < 8; nb++) {
            const int col0 = bn * 128 + warpN * 64 + nb * 8 + 2 * tig;
            const float bx = bias[col0];
            const float by = bias[col0 + 1];
            float4 c = acc[mb][nb];
            if (MODE == 0) {
                float2 v0 = make_float2(c.x + bx, c.y + by);
                float2 v1 = make_float2(c.z + bx, c.w + by);
                *reinterpret_cast<float2*>(&C[(size_t)row0 * DIM + col0]) = v0;
                *reinterpret_cast<float2*>(&C[(size_t)(row0 + 8) * DIM + col0]) = v1;
            } else {
                const int h  = col0 >> 6;
                const int d  = col0 & 63;
#pragma unroll
                for (int rr = 0; rr < 2; rr++) {
                    const int m = row0 + 8 * rr;
                    const int b = m >> 11;
                    const int s = m & (SEQ - 1);
                    float* dst = &C[(((size_t)(b * HEADS + h)) * SEQ + s) * HDIM + d];
                    dst[0] = (rr ? c.z : c.x) + bx;
                    dst[1] = (rr ? c.w : c.y) + by;
                }
            }
        }
    }
}

// ---------------------------------------------------------------------------
// Flash attention (fp32, packed f32x2 FMA). Grid: (S/128, H, B). 128 threads.
// Q,K,V in [B,H,S,DH]; writes ctx in [B,S,H*DH].
// ---------------------------------------------------------------------------
__global__ __launch_bounds__(128)
void flash_attn(const float* __restrict__ Q,
                const float* __restrict__ Kk,
                const float* __restrict__ V,
                const float* __restrict__ mask,
                float* __restrict__ ctx)
{
    __shared__ ulonglong2 Ks[64][16];
    __shared__ ulonglong2 Vs[64][16];
    __shared__ float mk[64];

    const int tid = threadIdx.x;
    const int qt  = blockIdx.x;
    const int h   = blockIdx.y;
    const int b   = blockIdx.z;

    const int q = qt * 128 + tid;
    const size_t headBase = ((size_t)(b * HEADS + h)) * SEQ;

    ulonglong2 qv[16];
    const ulonglong2* Q2 = reinterpret_cast<const ulonglong2*>(Q + (headBase + q) * HDIM);
#pragma unroll
    for (int c = 0; c < 16; c++) qv[c] = Q2[c];

    ulonglong2 acc[16];
#pragma unroll
    for (int c = 0; c < 16; c++) { acc[c].x = 0ull; acc[c].y = 0ull; }
    float mmax = -1e30f;
    float l = 0.f;

    const ulonglong2* K2 = reinterpret_cast<const ulonglong2*>(Kk);
    const ulonglong2* V2 = reinterpret_cast<const ulonglong2*>(V);

    for (int kt = 0; kt < SEQ / 64; kt++) {
        __syncthreads();
#pragma unroll
        for (int r = 0; r < 8; r++) {
            const int idx = r * 128 + tid;     // 0..1023
            const int row = idx >> 4;
            const int c   = idx & 15;
            const size_t gidx = (headBase + kt * 64 + row) * 16 + c;
            Ks[row][c] = K2[gidx];
            Vs[row][c] = V2[gidx];
        }
        if (tid < 64) mk[tid] = mask[(size_t)b * SEQ + kt * 64 + tid];
        __syncthreads();

#pragma unroll 2
        for (int j = 0; j < 64; j++) {
            u64 sA = 0ull, sB = 0ull;
#pragma unroll
            for (int c = 0; c < 16; c++) {
                ulonglong2 kk = Ks[j][c];
                ffma2(sA, kk.x, qv[c].x);
                ffma2(sB, kk.y, qv[c].y);
            }
            float x0, x1, x2, x3;
            unpack2(sA, x0, x1);
            unpack2(sB, x2, x3);
            float s = ((x0 + x1) + (x2 + x3)) * 0.125f
                      - 1000000.0f * (1.0f - mk[j]);
            if (s > mmax) {
                const float corr = __expf(mmax - s);
                l *= corr;
                const u64 cc = pack2(corr, corr);
#pragma unroll
                for (int c = 0; c < 16; c++) {
                    fmul2(acc[c].x, acc[c].x, cc);
                    fmul2(acc[c].y, acc[c].y, cc);
                }
                mmax = s;
            }
            const float p = __expf(s - mmax);
            l += p;
            const u64 pp = pack2(p, p);
#pragma unroll
            for (int c = 0; c < 16; c++) {
                ulonglong2 vv = Vs[j][c];
                ffma2(acc[c].x, pp, vv.x);
                ffma2(acc[c].y, pp, vv.y);
            }
        }
    }

    const float inv = 1.0f / l;
    const u64 ii = pack2(inv, inv);
    ulonglong2* out2 = reinterpret_cast<ulonglong2*>(ctx) +
                       ((size_t)(b * SEQ + q) * DIM + h * HDIM) / 4;
#pragma unroll
    for (int c = 0; c < 16; c++) {
        ulonglong2 v;
        fmul2(v.x, acc[c].x, ii);
        fmul2(v.y, acc[c].y, ii);
        out2[c] = v;
    }
}

// ---------------------------------------------------------------------------
// Launch
// ---------------------------------------------------------------------------
extern "C" void kernel_launch(void* const* d_in, const int* in_sizes, int n_in,
                              void* d_out, int out_size)
{
    const float* X    = (const float*)d_in[0];
    const float* mask = (const float*)d_in[1];
    const float* Wq   = (const float*)d_in[2];
    const float* bq   = (const float*)d_in[3];
    const float* Wk   = (const float*)d_in[4];
    const float* bk   = (const float*)d_in[5];
    const float* Wv   = (const float*)d_in[6];
    const float* bv   = (const float*)d_in[7];
    const float* Wo   = (const float*)d_in[8];
    const float* bo   = (const float*)d_in[9];
    float* out = (float*)d_out;

    float *Qp, *Kp, *Vp, *Cp;
    cudaGetSymbolAddress((void**)&Qp, g_Q);
    cudaGetSymbolAddress((void**)&Kp, g_K);
    cudaGetSymbolAddress((void**)&Vp, g_V);
    cudaGetSymbolAddress((void**)&Cp, g_ctx);

    dim3 gemmGrid(DIM / 128, MROWS / 128);   // (8, 32)
    gemm_bf16s<1><<<gemmGrid, 256>>>(X, Wq, bq, Qp);
    gemm_bf16s<1><<<gemmGrid, 256>>>(X, Wk, bk, Kp);
    gemm_bf16s<1><<<gemmGrid, 256>>>(X, Wv, bv, Vp);

    dim3 attnGrid(SEQ / 128, HEADS, BATCH);  // (16, 16, 2)
    flash_attn<<<attnGrid, 128>>>(Qp, Kp, Vp, mask, Cp);

    gemm_bf16s<0><<<gemmGrid, 256>>>(Cp, Wo, bo, out);
}

// round 7
// speedup vs baseline: 4.4026x; 2.5422x over previous
#include <cuda_runtime.h>
#include <cuda_bf16.h>

// Problem constants
#define BATCH 2
#define SEQ   2048
#define DIM   1024
#define HEADS 16
#define HDIM  64
#define MROWS (BATCH * SEQ)   // 4096

typedef unsigned long long u64;

// Scratch (allocation-free rule: __device__ globals)
__device__ float g_Q[BATCH * HEADS * SEQ * HDIM];   // [B,H,S,DH]
__device__ float g_K[BATCH * HEADS * SEQ * HDIM];
__device__ float g_V[BATCH * HEADS * SEQ * HDIM];
__device__ float g_ctx[BATCH * SEQ * DIM];          // [B,S,H*DH]

// ---------------------------------------------------------------------------
// Helpers
// ---------------------------------------------------------------------------
__device__ __forceinline__ void mma_bf16(float4& d,
                                         unsigned a0, unsigned a1, unsigned a2, unsigned a3,
                                         unsigned b0, unsigned b1)
{
    asm volatile("mma.sync.aligned.m16n8k16.row.col.f32.bf16.bf16.f32 "
                 "{%0,%1,%2,%3}, {%4,%5,%6,%7}, {%8,%9}, {%0,%1,%2,%3};"
                 : "+f"(d.x), "+f"(d.y), "+f"(d.z), "+f"(d.w)
                 : "r"(a0), "r"(a1), "r"(a2), "r"(a3), "r"(b0), "r"(b1));
}

// split fp32 pair into packed bf16x2 (hi) and bf16x2 (lo = residual)
__device__ __forceinline__ void split_pack(float x, float y, unsigned& hi, unsigned& lo)
{
    __nv_bfloat16 bx = __float2bfloat16(x);
    __nv_bfloat16 by = __float2bfloat16(y);
    float lx = x - __bfloat162float(bx);
    float ly = y - __bfloat162float(by);
    __nv_bfloat162 h = __halves2bfloat162(bx, by);
    __nv_bfloat162 l = __floats2bfloat162_rn(lx, ly);
    hi = reinterpret_cast<unsigned&>(h);
    lo = reinterpret_cast<unsigned&>(l);
}

// ---------------------------------------------------------------------------
// GEMM via bf16-split tensor-core mma (3-term compensated, ~1e-5 rel err)
// C[4096,1024] = A[4096,1024] @ W[1024,1024] + bias
// Block tile 128x128xBK16, 256 threads, 8 warps 4(m)x2(n), warp tile 32x64.
// MODE 0: row-major write. MODE 1: split-head write to [B,H,S,DH].
// ---------------------------------------------------------------------------
#define SSTRIDE 136

template <int MODE>
__global__ __launch_bounds__(256, 2)
void gemm_bf16s(const float* __restrict__ A,
                const float* __restrict__ W,
                const float* __restrict__ bias,
                float* __restrict__ C)
{
    __shared__ unsigned AsH[2][8 * SSTRIDE];
    __shared__ unsigned AsL[2][8 * SSTRIDE];
    __shared__ unsigned BsH[2][8 * SSTRIDE];
    __shared__ unsigned BsL[2][8 * SSTRIDE];

    const int tid   = threadIdx.x;
    const int lane  = tid & 31;
    const int warp  = tid >> 5;
    const int warpM = warp >> 1;
    const int warpN = warp & 1;
    const int g     = lane >> 2;
    const int tig   = lane & 3;

    const int bm = blockIdx.y;
    const int bn = blockIdx.x;

    const int aRow = tid >> 2;
    const int aK4  = tid & 3;
    const int bN   = tid & 127;
    const int bK2  = tid >> 7;

    float4 ra[2];
    float  rb[4][2];

    {
        const float* Ap = A + (size_t)(bm * 128 + aRow) * DIM + aK4 * 4;
        ra[0] = *reinterpret_cast<const float4*>(Ap);
        ra[1] = *reinterpret_cast<const float4*>(Ap + (size_t)64 * DIM);
#pragma unroll
        for (int p = 0; p < 4; p++) {
            const int k2 = bK2 + 2 * p;
            const float* Wp = W + (size_t)(2 * k2) * DIM + bn * 128 + bN;
            rb[p][0] = Wp[0];
            rb[p][1] = Wp[DIM];
        }
    }
    {
#pragma unroll
        for (int p = 0; p < 2; p++) {
            const int m = aRow + 64 * p;
            unsigned h0, l0, h1, l1;
            split_pack(ra[p].x, ra[p].y, h0, l0);
            split_pack(ra[p].z, ra[p].w, h1, l1);
            AsH[0][(aK4 * 2 + 0) * SSTRIDE + m] = h0;
            AsL[0][(aK4 * 2 + 0) * SSTRIDE + m] = l0;
            AsH[0][(aK4 * 2 + 1) * SSTRIDE + m] = h1;
            AsL[0][(aK4 * 2 + 1) * SSTRIDE + m] = l1;
        }
#pragma unroll
        for (int p = 0; p < 4; p++) {
            const int k2 = bK2 + 2 * p;
            unsigned h, l;
            split_pack(rb[p][0], rb[p][1], h, l);
            BsH[0][k2 * SSTRIDE + bN] = h;
            BsL[0][k2 * SSTRIDE + bN] = l;
        }
    }
    __syncthreads();

    float4 acc[2][8];
#pragma unroll
    for (int i = 0; i < 2; i++)
#pragma unroll
        for (int j = 0; j < 8; j++) acc[i][j] = make_float4(0.f, 0.f, 0.f, 0.f);

    const int NK = DIM / 16;
    for (int kt = 0; kt < NK; kt++) {
        const int buf = kt & 1;

        if (kt < NK - 1) {
            const int k0 = (kt + 1) * 16;
            const float* Ap = A + (size_t)(bm * 128 + aRow) * DIM + k0 + aK4 * 4;
            ra[0] = *reinterpret_cast<const float4*>(Ap);
            ra[1] = *reinterpret_cast<const float4*>(Ap + (size_t)64 * DIM);
#pragma unroll
            for (int p = 0; p < 4; p++) {
                const int k2 = bK2 + 2 * p;
                const float* Wp = W + (size_t)(k0 + 2 * k2) * DIM + bn * 128 + bN;
                rb[p][0] = Wp[0];
                rb[p][1] = Wp[DIM];
            }
        }

        unsigned aH[2][4], aL[2][4];
#pragma unroll
        for (int mb = 0; mb < 2; mb++) {
            const int m0 = warpM * 32 + mb * 16 + g;
            aH[mb][0] = AsH[buf][tig * SSTRIDE + m0];
            aH[mb][1] = AsH[buf][tig * SSTRIDE + m0 + 8];
            aH[mb][2] = AsH[buf][(tig + 4) * SSTRIDE + m0];
            aH[mb][3] = AsH[buf][(tig + 4) * SSTRIDE + m0 + 8];
            aL[mb][0] = AsL[buf][tig * SSTRIDE + m0];
            aL[mb][1] = AsL[buf][tig * SSTRIDE + m0 + 8];
            aL[mb][2] = AsL[buf][(tig + 4) * SSTRIDE + m0];
            aL[mb][3] = AsL[buf][(tig + 4) * SSTRIDE + m0 + 8];
        }
#pragma unroll
        for (int nb = 0; nb < 8; nb++) {
            const int n0 = warpN * 64 + nb * 8 + g;
            const unsigned bh0 = BsH[buf][tig * SSTRIDE + n0];
            const unsigned bh1 = BsH[buf][(tig + 4) * SSTRIDE + n0];
            const unsigned bl0 = BsL[buf][tig * SSTRIDE + n0];
            const unsigned bl1 = BsL[buf][(tig + 4) * SSTRIDE + n0];
#pragma unroll
            for (int mb = 0; mb < 2; mb++) {
                mma_bf16(acc[mb][nb], aH[mb][0], aH[mb][1], aH[mb][2], aH[mb][3], bh0, bh1);
                mma_bf16(acc[mb][nb], aH[mb][0], aH[mb][1], aH[mb][2], aH[mb][3], bl0, bl1);
                mma_bf16(acc[mb][nb], aL[mb][0], aL[mb][1], aL[mb][2], aL[mb][3], bh0, bh1);
            }
        }

        if (kt < NK - 1) {
            const int nbuf = buf ^ 1;
#pragma unroll
            for (int p = 0; p < 2; p++) {
                const int m = aRow + 64 * p;
                unsigned h0, l0, h1, l1;
                split_pack(ra[p].x, ra[p].y, h0, l0);
                split_pack(ra[p].z, ra[p].w, h1, l1);
                AsH[nbuf][(aK4 * 2 + 0) * SSTRIDE + m] = h0;
                AsL[nbuf][(aK4 * 2 + 0) * SSTRIDE + m] = l0;
                AsH[nbuf][(aK4 * 2 + 1) * SSTRIDE + m] = h1;
                AsL[nbuf][(aK4 * 2 + 1) * SSTRIDE + m] = l1;
            }
#pragma unroll
            for (int p = 0; p < 4; p++) {
                const int k2 = bK2 + 2 * p;
                unsigned h, l;
                split_pack(rb[p][0], rb[p][1], h, l);
                BsH[nbuf][k2 * SSTRIDE + bN] = h;
                BsL[nbuf][k2 * SSTRIDE + bN] = l;
            }
        }
        __syncthreads();
    }

#pragma unroll
    for (int mb = 0; mb < 2; mb++) {
        const int row0 = bm * 128 + warpM * 32 + mb * 16 + g;
#pragma unroll
        for (int nb = 0; nb < 8; nb++) {
            const int col0 = bn * 128 + warpN * 64 + nb * 8 + 2 * tig;
            const float bx = bias[col0];
            const float by = bias[col0 + 1];
            float4 c = acc[mb][nb];
            if (MODE == 0) {
                float2 v0 = make_float2(c.x + bx, c.y + by);
                float2 v1 = make_float2(c.z + bx, c.w + by);
                *reinterpret_cast<float2*>(&C[(size_t)row0 * DIM + col0]) = v0;
                *reinterpret_cast<float2*>(&C[(size_t)(row0 + 8) * DIM + col0]) = v1;
            } else {
                const int h  = col0 >> 6;
                const int d  = col0 & 63;
#pragma unroll
                for (int rr = 0; rr < 2; rr++) {
                    const int m = row0 + 8 * rr;
                    const int b = m >> 11;
                    const int s = m & (SEQ - 1);
                    float* dst = &C[(((size_t)(b * HEADS + h)) * SEQ + s) * HDIM + d];
                    dst[0] = (rr ? c.z : c.x) + bx;
                    dst[1] = (rr ? c.w : c.y) + by;
                }
            }
        }
    }
}

// ---------------------------------------------------------------------------
// Flash attention on tensor cores (bf16-split, 3-term).
// Block: 64 queries x 1 head, 4 warps (each warp 16 query rows).
// Grid: (S/64, H, B) = (32,16,2) = 1024 blocks.
// K tile in smem as [key][dh-pair] split hi/lo; V transposed [dh][key-pair].
// Stride 36 words => conflict-free fragment loads (bank = 4*row+tig).
// ---------------------------------------------------------------------------
#define FS 36

__global__ __launch_bounds__(128)
void flash_attn_mma(const float* __restrict__ Q,
                    const float* __restrict__ Kk,
                    const float* __restrict__ V,
                    const float* __restrict__ mask,
                    float* __restrict__ ctx)
{
    __shared__ unsigned KH[64 * FS];
    __shared__ unsigned KL[64 * FS];
    __shared__ unsigned VtH[64 * FS];
    __shared__ unsigned VtL[64 * FS];
    __shared__ float neg[64];

    const int tid  = threadIdx.x;
    const int lane = tid & 31;
    const int warp = tid >> 5;       // 0..3 -> query rows warp*16..+15
    const int g    = lane >> 2;      // 0..7
    const int tig  = lane & 3;       // 0..3

    const int qt = blockIdx.x;
    const int h  = blockIdx.y;
    const int b  = blockIdx.z;
    const int q0 = qt * 64;
    const size_t headBase = ((size_t)(b * HEADS + h)) * SEQ;

    // ---- stage Q (scaled by 1/8), split into KH/KL as scratch ----
#pragma unroll
    for (int i = 0; i < 16; i++) {
        const int e    = i * 128 + tid;    // 0..2047
        const int row  = e >> 5;           // 0..63
        const int pair = e & 31;           // 0..31
        float2 v = *reinterpret_cast<const float2*>(
            Q + (headBase + q0 + row) * HDIM + pair * 2);
        unsigned hh, ll;
        split_pack(v.x * 0.125f, v.y * 0.125f, hh, ll);
        KH[row * FS + pair] = hh;
        KL[row * FS + pair] = ll;
    }
    __syncthreads();

    // per-warp Q fragments (4 k-chunks of 16)
    unsigned qaH[4][4], qaL[4][4];
#pragma unroll
    for (int kc = 0; kc < 4; kc++) {
        const int r0 = (warp * 16 + g) * FS;
        const int r1 = (warp * 16 + g + 8) * FS;
        qaH[kc][0] = KH[r0 + kc * 8 + tig];
        qaH[kc][1] = KH[r1 + kc * 8 + tig];
        qaH[kc][2] = KH[r0 + kc * 8 + tig + 4];
        qaH[kc][3] = KH[r1 + kc * 8 + tig + 4];
        qaL[kc][0] = KL[r0 + kc * 8 + tig];
        qaL[kc][1] = KL[r1 + kc * 8 + tig];
        qaL[kc][2] = KL[r0 + kc * 8 + tig + 4];
        qaL[kc][3] = KL[r1 + kc * 8 + tig + 4];
    }

    float4 o[8];
#pragma unroll
    for (int nb = 0; nb < 8; nb++) o[nb] = make_float4(0.f, 0.f, 0.f, 0.f);
    float m0 = -1e30f, m1 = -1e30f;
    float l0 = 0.f, l1 = 0.f;

    for (int kt = 0; kt < SEQ / 64; kt++) {
        __syncthreads();   // protect smem reuse
        // ---- stage K tile: [key][dh-pair] split ----
#pragma unroll
        for (int i = 0; i < 16; i++) {
            const int e    = i * 128 + tid;
            const int row  = e >> 5;
            const int pair = e & 31;
            float2 v = *reinterpret_cast<const float2*>(
                Kk + (headBase + kt * 64 + row) * HDIM + pair * 2);
            unsigned hh, ll;
            split_pack(v.x, v.y, hh, ll);
            KH[row * FS + pair] = hh;
            KL[row * FS + pair] = ll;
        }
        // ---- stage V tile transposed: Vt[dh][key-pair] split ----
#pragma unroll
        for (int i = 0; i < 16; i++) {
            const int e  = i * 128 + tid;
            const int dh = e & 63;
            const int kp = e >> 6;          // 0..31
            const float v0 = V[(headBase + kt * 64 + 2 * kp) * HDIM + dh];
            const float v1 = V[(headBase + kt * 64 + 2 * kp + 1) * HDIM + dh];
            unsigned hh, ll;
            split_pack(v0, v1, hh, ll);
            VtH[dh * FS + kp] = hh;
            VtL[dh * FS + kp] = ll;
        }
        if (tid < 64)
            neg[tid] = -1000000.0f * (1.0f - mask[(size_t)b * SEQ + kt * 64 + tid]);
        __syncthreads();

        // ---- scores: S = Q K^T (3-term bf16 mma) ----
        float4 sc[8];
#pragma unroll
        for (int nb = 0; nb < 8; nb++) {
            sc[nb] = make_float4(0.f, 0.f, 0.f, 0.f);
#pragma unroll
            for (int kc = 0; kc < 4; kc++) {
                const int kb = (nb * 8 + g) * FS + kc * 8 + tig;
                const unsigned bh0 = KH[kb];
                const unsigned bh1 = KH[kb + 4];
                const unsigned bl0 = KL[kb];
                const unsigned bl1 = KL[kb + 4];
                mma_bf16(sc[nb], qaH[kc][0], qaH[kc][1], qaH[kc][2], qaH[kc][3], bh0, bh1);
                mma_bf16(sc[nb], qaH[kc][0], qaH[kc][1], qaH[kc][2], qaH[kc][3], bl0, bl1);
                mma_bf16(sc[nb], qaL[kc][0], qaL[kc][1], qaL[kc][2], qaL[kc][3], bh0, bh1);
            }
        }

        // ---- mask + online softmax ----
        float tmax0 = -1e30f, tmax1 = -1e30f;
#pragma unroll
        for (int nb = 0; nb < 8; nb++) {
            const float n0 = neg[nb * 8 + 2 * tig];
            const float n1 = neg[nb * 8 + 2 * tig + 1];
            sc[nb].x += n0; sc[nb].y += n1;
            sc[nb].z += n0; sc[nb].w += n1;
            tmax0 = fmaxf(tmax0, fmaxf(sc[nb].x, sc[nb].y));
            tmax1 = fmaxf(tmax1, fmaxf(sc[nb].z, sc[nb].w));
        }
        tmax0 = fmaxf(tmax0, __shfl_xor_sync(0xffffffffu, tmax0, 1));
        tmax0 = fmaxf(tmax0, __shfl_xor_sync(0xffffffffu, tmax0, 2));
        tmax1 = fmaxf(tmax1, __shfl_xor_sync(0xffffffffu, tmax1, 1));
        tmax1 = fmaxf(tmax1, __shfl_xor_sync(0xffffffffu, tmax1, 2));

        const float nm0 = fmaxf(m0, tmax0);
        const float nm1 = fmaxf(m1, tmax1);
        const float corr0 = __expf(m0 - nm0);
        const float corr1 = __expf(m1 - nm1);
        m0 = nm0; m1 = nm1;

        float r0 = 0.f, r1 = 0.f;
#pragma unroll
        for (int nb = 0; nb < 8; nb++) {
            sc[nb].x = __expf(sc[nb].x - nm0);
            sc[nb].y = __expf(sc[nb].y - nm0);
            sc[nb].z = __expf(sc[nb].z - nm1);
            sc[nb].w = __expf(sc[nb].w - nm1);
            r0 += sc[nb].x + sc[nb].y;
            r1 += sc[nb].z + sc[nb].w;
        }
        r0 += __shfl_xor_sync(0xffffffffu, r0, 1);
        r0 += __shfl_xor_sync(0xffffffffu, r0, 2);
        r1 += __shfl_xor_sync(0xffffffffu, r1, 1);
        r1 += __shfl_xor_sync(0xffffffffu, r1, 2);
        l0 = l0 * corr0 + r0;
        l1 = l1 * corr1 + r1;

        // rescale O
#pragma unroll
        for (int nb = 0; nb < 8; nb++) {
            o[nb].x *= corr0; o[nb].y *= corr0;
            o[nb].z *= corr1; o[nb].w *= corr1;
        }

        // ---- pack P into A-fragments (C-frag layout == A-frag layout) ----
        unsigned pH[4][4], pL[4][4];
#pragma unroll
        for (int kc = 0; kc < 4; kc++) {
            split_pack(sc[2 * kc].x,     sc[2 * kc].y,     pH[kc][0], pL[kc][0]);
            split_pack(sc[2 * kc].z,     sc[2 * kc].w,     pH[kc][1], pL[kc][1]);
            split_pack(sc[2 * kc + 1].x, sc[2 * kc + 1].y, pH[kc][2], pL[kc][2]);
            split_pack(sc[2 * kc + 1].z, sc[2 * kc + 1].w, pH[kc][3], pL[kc][3]);
        }

        // ---- O += P V (3-term bf16 mma) ----
#pragma unroll
        for (int nb = 0; nb < 8; nb++) {
#pragma unroll
            for (int kc = 0; kc < 4; kc++) {
                const int vb = (nb * 8 + g) * FS + kc * 8 + tig;
                const unsigned vh0 = VtH[vb];
                const unsigned vh1 = VtH[vb + 4];
                const unsigned vl0 = VtL[vb];
                const unsigned vl1 = VtL[vb + 4];
                mma_bf16(o[nb], pH[kc][0], pH[kc][1], pH[kc][2], pH[kc][3], vh0, vh1);
                mma_bf16(o[nb], pH[kc][0], pH[kc][1], pH[kc][2], pH[kc][3], vl0, vl1);
                mma_bf16(o[nb], pL[kc][0], pL[kc][1], pL[kc][2], pL[kc][3], vh0, vh1);
            }
        }
    }

    // ---- epilogue: O /= l, write ctx [B,S,H*DH] ----
    const float inv0 = 1.0f / l0;
    const float inv1 = 1.0f / l1;
    const int qr0 = q0 + warp * 16 + g;
    const int qr1 = qr0 + 8;
#pragma unroll
    for (int nb = 0; nb < 8; nb++) {
        const int col = h * HDIM + nb * 8 + 2 * tig;
        float2 v0 = make_float2(o[nb].x * inv0, o[nb].y * inv0);
        float2 v1 = make_float2(o[nb].z * inv1, o[nb].w * inv1);
        *reinterpret_cast<float2*>(&ctx[((size_t)(b * SEQ) + qr0) * DIM + col]) = v0;
        *reinterpret_cast<float2*>(&ctx[((size_t)(b * SEQ) + qr1) * DIM + col]) = v1;
    }
}

// ---------------------------------------------------------------------------
// Launch
// ---------------------------------------------------------------------------
extern "C" void kernel_launch(void* const* d_in, const int* in_sizes, int n_in,
                              void* d_out, int out_size)
{
    const float* X    = (const float*)d_in[0];
    const float* mask = (const float*)d_in[1];
    const float* Wq   = (const float*)d_in[2];
    const float* bq   = (const float*)d_in[3];
    const float* Wk   = (const float*)d_in[4];
    const float* bk   = (const float*)d_in[5];
    const float* Wv   = (const float*)d_in[6];
    const float* bv   = (const float*)d_in[7];
    const float* Wo   = (const float*)d_in[8];
    const float* bo   = (const float*)d_in[9];
    float* out = (float*)d_out;

    float *Qp, *Kp, *Vp, *Cp;
    cudaGetSymbolAddress((void**)&Qp, g_Q);
    cudaGetSymbolAddress((void**)&Kp, g_K);
    cudaGetSymbolAddress((void**)&Vp, g_V);
    cudaGetSymbolAddress((void**)&Cp, g_ctx);

    dim3 gemmGrid(DIM / 128, MROWS / 128);   // (8, 32)
    gemm_bf16s<1><<<gemmGrid, 256>>>(X, Wq, bq, Qp);
    gemm_bf16s<1><<<gemmGrid, 256>>>(X, Wk, bk, Kp);
    gemm_bf16s<1><<<gemmGrid, 256>>>(X, Wv, bv, Vp);

    dim3 attnGrid(SEQ / 64, HEADS, BATCH);   // (32, 16, 2)
    flash_attn_mma<<<attnGrid, 128>>>(Qp, Kp, Vp, mask, Cp);

    gemm_bf16s<0><<<gemmGrid, 256>>>(Cp, Wo, bo, out);
}